// round 1
// baseline (speedup 1.0000x reference)
#include <cuda_runtime.h>

#define BB 128          // graphs
#define NN 68           // landmarks per graph
#define CC 3            // input channels
#define PP 32           // patch
#define KK 16           // conv kernels
#define FD 64           // feature dim
#define GH 128          // gcn hidden
#define OUTD 2
#define EG (8*NN)       // 544 edges per graph
#define TT (BB*NN)      // 8704 nodes
#define FLAT (KK*(PP/2)*(PP/2))   // 4096

// ---- scratch (allocation-free: device globals) ----
__device__ float g_flat[(size_t)TT * FLAT];   // ~142.6 MB
__device__ float g_feats[TT * FD];
__device__ float g_xw[TT * GH];
__device__ float g_dis[TT];
__device__ float g_h[TT * GH];

// ============================================================
// Stage 1: per-landmark conv3x3 (SAME) + bias + relu + maxpool2x2
// one block per node t; 256 threads = one pooled pixel each; loop k
// ============================================================
__global__ __launch_bounds__(256) void conv_pool_kernel(
    const float* __restrict__ x,
    const float* __restrict__ conv_w,
    const float* __restrict__ conv_b)
{
    int t = blockIdx.x;
    int n = t % NN;
    __shared__ float xs[CC][PP][PP];     // 12 KB
    __shared__ float ws[27];
    __shared__ float bs;

    int tid = threadIdx.x;
    const float* xp = x + (size_t)t * (CC * PP * PP);
    for (int i = tid; i < CC * PP * PP; i += 256)
        ((float*)xs)[i] = xp[i];

    int pi = tid >> 4;          // pooled row 0..15
    int pj = tid & 15;          // pooled col 0..15

    for (int k = 0; k < KK; k++) {
        __syncthreads();        // xs ready (k=0) / prev ws reads done
        if (tid < 27) ws[tid] = conv_w[(n * KK + k) * 27 + tid];
        if (tid == 31) bs = conv_b[n * KK + k];
        __syncthreads();

        float m = 0.f;          // relu outputs are >= 0
        #pragma unroll
        for (int s = 0; s < 4; s++) {
            int y0 = 2 * pi + (s >> 1);
            int x0 = 2 * pj + (s & 1);
            float acc = bs;
            #pragma unroll
            for (int c = 0; c < CC; c++) {
                #pragma unroll
                for (int dy = 0; dy < 3; dy++) {
                    int yy = y0 + dy - 1;
                    if (yy < 0 || yy >= PP) continue;
                    #pragma unroll
                    for (int dx = 0; dx < 3; dx++) {
                        int xx = x0 + dx - 1;
                        if (xx < 0 || xx >= PP) continue;
                        acc = fmaf(xs[c][yy][xx], ws[c * 9 + dy * 3 + dx], acc);
                    }
                }
            }
            acc = fmaxf(acc, 0.f);
            m = fmaxf(m, acc);
        }
        g_flat[(size_t)t * FLAT + k * 256 + tid] = m;
    }
}

// ============================================================
// Stage 2: per-landmark linear 4096 -> 64, relu
// grid (68, 4): block = (landmark n, slab of 32 graphs)
// 256 threads: o = tid&63, brow = tid>>6, 8 graphs per thread
// smem-tiled over f in chunks of 64
// ============================================================
__global__ __launch_bounds__(256) void lin1_kernel(
    const float* __restrict__ lin1_w,
    const float* __restrict__ lin1_b)
{
    int n  = blockIdx.x;
    int b0 = blockIdx.y * 32;
    __shared__ float wsh[64 * 64];      // [ff][o] 16 KB
    __shared__ float fsh[32][64];       // [bi][ff] 8 KB

    int tid  = threadIdx.x;
    int o    = tid & 63;
    int brow = tid >> 6;                // 0..3

    float acc[8];
    #pragma unroll
    for (int i = 0; i < 8; i++) acc[i] = 0.f;

    const float* wbase = lin1_w + (size_t)n * FLAT * FD;

    for (int f0 = 0; f0 < FLAT; f0 += 64) {
        __syncthreads();
        const float* wsrc = wbase + (size_t)f0 * FD;
        #pragma unroll
        for (int j = 0; j < 16; j++) {
            int idx = tid + j * 256;
            wsh[idx] = wsrc[idx];       // coalesced, same linear layout
        }
        #pragma unroll
        for (int j = 0; j < 8; j++) {
            int idx = tid + j * 256;
            int bi = idx >> 6, ff = idx & 63;
            fsh[bi][ff] = g_flat[(size_t)((b0 + bi) * NN + n) * FLAT + f0 + ff];
        }
        __syncthreads();
        #pragma unroll
        for (int ff = 0; ff < 64; ff++) {
            float wv = wsh[ff * 64 + o];
            #pragma unroll
            for (int i = 0; i < 8; i++)
                acc[i] = fmaf(fsh[brow * 8 + i][ff], wv, acc[i]);
        }
    }

    float bias = lin1_b[n * FD + o];
    #pragma unroll
    for (int i = 0; i < 8; i++) {
        int b = b0 + brow * 8 + i;
        g_feats[(size_t)(b * NN + n) * FD + o] = fmaxf(acc[i] + bias, 0.f);
    }
}

// ============================================================
// Stage 3: xw = feats @ gcn_w  [T,64] @ [64,128]
// ============================================================
__global__ __launch_bounds__(GH) void gcn_xw_kernel(const float* __restrict__ gcn_w)
{
    int t = blockIdx.x;
    __shared__ float fsm[FD];
    int j = threadIdx.x;
    if (j < FD) fsm[j] = g_feats[t * FD + j];
    __syncthreads();
    float acc = 0.f;
    #pragma unroll
    for (int c = 0; c < FD; c++)
        acc = fmaf(fsm[c], gcn_w[c * GH + j], acc);
    g_xw[t * GH + j] = acc;
}

// ============================================================
// Stage 4: degrees (incl self-loop) -> 1/sqrt(deg), deterministic scan
// ============================================================
__global__ void deg_kernel(const int* __restrict__ edge_index)
{
    int t = blockIdx.x * blockDim.x + threadIdx.x;
    if (t >= TT) return;
    const int* dst = edge_index + BB * EG;
    int base = (t / NN) * EG;
    int cnt = 1;                        // self loop
    for (int e = 0; e < EG; e++)
        cnt += (dst[base + e] == t);
    g_dis[t] = rsqrtf((float)cnt);
}

// ============================================================
// Stage 5: h[t] = relu( sum_{e: dst==t} norm_e * xw[src_e] + dis_t^2*xw[t] + b )
// block per node; deterministic (fixed edge order); no atomics
// ============================================================
__global__ __launch_bounds__(GH) void aggregate_kernel(
    const int* __restrict__ edge_index,
    const float* __restrict__ gcn_b)
{
    int t = blockIdx.x;
    int g = t / NN;
    const int* srcA = edge_index;
    const int* dstA = edge_index + BB * EG;

    __shared__ int   ssrc[EG];
    __shared__ float snorm[EG];

    int tid = threadIdx.x;              // channel 0..127
    float dis_t = g_dis[t];

    for (int e = tid; e < EG; e += GH) {
        int d = dstA[g * EG + e];
        int s = srcA[g * EG + e];
        ssrc[e]  = s;
        snorm[e] = (d == t) ? g_dis[s] * dis_t : 0.f;
    }
    __syncthreads();

    float acc = dis_t * dis_t * g_xw[t * GH + tid];   // self loop
    for (int e = 0; e < EG; e++) {
        float nm = snorm[e];
        if (nm != 0.f)
            acc = fmaf(nm, g_xw[ssrc[e] * GH + tid], acc);
    }
    g_h[t * GH + tid] = fmaxf(acc + gcn_b[tid], 0.f);
}

// ============================================================
// Stage 6: mean pool over 68 nodes + MLP 128->64 relu ->2
// ============================================================
__global__ __launch_bounds__(GH) void head_kernel(
    const float* __restrict__ w1, const float* __restrict__ b1,
    const float* __restrict__ w2, const float* __restrict__ b2,
    float* __restrict__ out)
{
    int b = blockIdx.x;
    int tid = threadIdx.x;
    __shared__ float gsm[GH];
    __shared__ float zsm[GH / 2];

    float s = 0.f;
    for (int i = 0; i < NN; i++)
        s += g_h[(b * NN + i) * GH + tid];
    gsm[tid] = s * (1.0f / (float)NN);
    __syncthreads();

    if (tid < GH / 2) {
        float acc = b1[tid];
        #pragma unroll
        for (int c = 0; c < GH; c++)
            acc = fmaf(gsm[c], w1[c * (GH / 2) + tid], acc);
        zsm[tid] = fmaxf(acc, 0.f);
    }
    __syncthreads();

    if (tid < OUTD) {
        float acc = b2[tid];
        for (int j = 0; j < GH / 2; j++)
            acc = fmaf(zsm[j], w2[j * OUTD + tid], acc);
        out[b * OUTD + tid] = acc;
    }
}

extern "C" void kernel_launch(void* const* d_in, const int* in_sizes, int n_in,
                              void* d_out, int out_size)
{
    const float* x        = (const float*)d_in[0];
    const int*   edge_idx = (const int*)  d_in[1];
    // d_in[2] = batch (implied by layout, unused)
    const float* conv_w   = (const float*)d_in[3];
    const float* conv_b   = (const float*)d_in[4];
    const float* lin1_w   = (const float*)d_in[5];
    const float* lin1_b   = (const float*)d_in[6];
    const float* gcn_w    = (const float*)d_in[7];
    const float* gcn_b    = (const float*)d_in[8];
    const float* mlp_w1   = (const float*)d_in[9];
    const float* mlp_b1   = (const float*)d_in[10];
    const float* mlp_w2   = (const float*)d_in[11];
    const float* mlp_b2   = (const float*)d_in[12];
    float* out = (float*)d_out;

    conv_pool_kernel<<<TT, 256>>>(x, conv_w, conv_b);
    lin1_kernel<<<dim3(NN, 4), 256>>>(lin1_w, lin1_b);
    gcn_xw_kernel<<<TT, GH>>>(gcn_w);
    deg_kernel<<<(TT + 255) / 256, 256>>>(edge_idx);
    aggregate_kernel<<<TT, GH>>>(edge_idx, gcn_b);
    head_kernel<<<BB, GH>>>(mlp_w1, mlp_b1, mlp_w2, mlp_b2, out);
}

// round 2
// speedup vs baseline: 2.0139x; 2.0139x over previous
#include <cuda_runtime.h>

#define BB 128          // graphs
#define NN 68           // landmarks per graph
#define CC 3            // input channels
#define PP 32           // patch
#define KK 16           // conv kernels
#define FD 64           // feature dim
#define GH 128          // gcn hidden
#define OUTD 2
#define EG (8*NN)       // 544 edges per graph
#define TT (BB*NN)      // 8704 nodes
#define FLAT (KK*(PP/2)*(PP/2))   // 4096

// ---- scratch (allocation-free: device globals) ----
__device__ float g_flat[(size_t)TT * FLAT];   // ~142.6 MB
__device__ float g_feats[TT * FD];
__device__ float g_xw[TT * GH];
__device__ float g_dis[TT];
__device__ float g_h[TT * GH];

// ============================================================
// Stage 1: per-landmark conv3x3 (SAME) + bias + relu + maxpool2x2
// block per node; thread = pooled pixel; 4x4x3 window in registers,
// reused across all 16 kernels (LDS per thread: 48 + 16*28)
// ============================================================
__global__ __launch_bounds__(256) void conv_pool_kernel(
    const float* __restrict__ x,
    const float* __restrict__ conv_w,
    const float* __restrict__ conv_b)
{
    int t = blockIdx.x;
    int n = t % NN;
    __shared__ float xs[CC][PP][PP];     // 12 KB
    __shared__ float ws[KK * 27 + KK];   // all 16 kernels + biases

    int tid = threadIdx.x;
    const float* xp = x + (size_t)t * (CC * PP * PP);
    #pragma unroll
    for (int i = 0; i < 12; i++)
        ((float*)xs)[tid + i * 256] = xp[tid + i * 256];
    for (int i = tid; i < KK * 27; i += 256)
        ws[i] = conv_w[(size_t)n * KK * 27 + i];
    if (tid < KK) ws[KK * 27 + tid] = conv_b[n * KK + tid];
    __syncthreads();

    int pi = tid >> 4, pj = tid & 15;
    int y0 = 2 * pi, x0 = 2 * pj;

    // 4x4x3 window, zero-padded at borders
    float win[CC][4][4];
    #pragma unroll
    for (int c = 0; c < CC; c++)
        #pragma unroll
        for (int dy = 0; dy < 4; dy++) {
            int yy = y0 + dy - 1;
            #pragma unroll
            for (int dx = 0; dx < 4; dx++) {
                int xx = x0 + dx - 1;
                win[c][dy][dx] = (yy >= 0 && yy < PP && xx >= 0 && xx < PP)
                                 ? xs[c][yy][xx] : 0.f;
            }
        }

    float* outp = &g_flat[(size_t)t * FLAT + tid];
    #pragma unroll 1
    for (int k = 0; k < KK; k++) {
        const float* w = &ws[k * 27];
        float b = ws[KK * 27 + k];
        float a00 = b, a01 = b, a10 = b, a11 = b;
        #pragma unroll
        for (int c = 0; c < CC; c++)
            #pragma unroll
            for (int dy = 0; dy < 3; dy++)
                #pragma unroll
                for (int dx = 0; dx < 3; dx++) {
                    float wv = w[c * 9 + dy * 3 + dx];
                    a00 = fmaf(win[c][dy    ][dx    ], wv, a00);
                    a01 = fmaf(win[c][dy    ][dx + 1], wv, a01);
                    a10 = fmaf(win[c][dy + 1][dx    ], wv, a10);
                    a11 = fmaf(win[c][dy + 1][dx + 1], wv, a11);
                }
        // max(relu(.)) == relu(max(.))
        float m = fmaxf(fmaxf(a00, a01), fmaxf(a10, a11));
        outp[k * 256] = fmaxf(m, 0.f);
    }
}

// ============================================================
// Stage 2: per-landmark linear 4096 -> 64, relu
// grid (68,4): 32-graph slab; float4 over ff, 32 FMA per 12 LDS
// ============================================================
__global__ __launch_bounds__(256) void lin1_kernel(
    const float* __restrict__ lin1_w,
    const float* __restrict__ lin1_b)
{
    int n  = blockIdx.x;
    int b0 = blockIdx.y * 32;
    __shared__ float  wsh[64 * 64];      // [ff][o]   16 KB
    __shared__ float4 fsh4[32 * 16];     // [bi][ff/4] 8 KB
    float* fsh = (float*)fsh4;

    int tid  = threadIdx.x;
    int o    = tid & 63;
    int brow = tid >> 6;                 // 0..3

    float acc[8];
    #pragma unroll
    for (int i = 0; i < 8; i++) acc[i] = 0.f;

    const float* wbase = lin1_w + (size_t)n * FLAT * FD;

    for (int f0 = 0; f0 < FLAT; f0 += 64) {
        __syncthreads();
        const float* wsrc = wbase + (size_t)f0 * FD;
        #pragma unroll
        for (int j = 0; j < 16; j++)
            wsh[tid + j * 256] = wsrc[tid + j * 256];
        #pragma unroll
        for (int j = 0; j < 8; j++) {
            int idx = tid + j * 256;
            int bi = idx >> 6, ff = idx & 63;
            fsh[idx] = g_flat[(size_t)((b0 + bi) * NN + n) * FLAT + f0 + ff];
        }
        __syncthreads();
        #pragma unroll 4
        for (int gquad = 0; gquad < 16; gquad++) {
            float w0 = wsh[(4 * gquad + 0) * 64 + o];
            float w1 = wsh[(4 * gquad + 1) * 64 + o];
            float w2 = wsh[(4 * gquad + 2) * 64 + o];
            float w3 = wsh[(4 * gquad + 3) * 64 + o];
            #pragma unroll
            for (int i = 0; i < 8; i++) {
                float4 fv = fsh4[(brow * 8 + i) * 16 + gquad];
                acc[i] = fmaf(fv.x, w0, acc[i]);
                acc[i] = fmaf(fv.y, w1, acc[i]);
                acc[i] = fmaf(fv.z, w2, acc[i]);
                acc[i] = fmaf(fv.w, w3, acc[i]);
            }
        }
    }

    float bias = lin1_b[n * FD + o];
    #pragma unroll
    for (int i = 0; i < 8; i++) {
        int b = b0 + brow * 8 + i;
        g_feats[(size_t)(b * NN + n) * FD + o] = fmaxf(acc[i] + bias, 0.f);
    }
}

// ============================================================
// Stage 3: xw = feats @ gcn_w   (4 nodes / block, gcn_w in smem)
// ============================================================
__global__ __launch_bounds__(512) void gcn_xw_kernel(const float* __restrict__ gcn_w)
{
    int t0 = blockIdx.x * 4;
    __shared__ float wsm[FD * GH];       // 32 KB
    __shared__ float fsm[4 * FD];
    int tid = threadIdx.x;
    #pragma unroll
    for (int i = 0; i < 16; i++)
        wsm[tid + i * 512] = gcn_w[tid + i * 512];
    if (tid < 4 * FD) fsm[tid] = g_feats[t0 * FD + tid];
    __syncthreads();

    int j = tid & 127, nd = tid >> 7;
    float acc = 0.f;
    #pragma unroll
    for (int c = 0; c < FD; c++)
        acc = fmaf(fsm[nd * FD + c], wsm[c * GH + j], acc);
    g_xw[(t0 + nd) * GH + j] = acc;
}

// ============================================================
// Stage 4: degree histogram per graph (int atomics = deterministic)
// ============================================================
__global__ __launch_bounds__(256) void deg_kernel(const int* __restrict__ edge_index)
{
    int g = blockIdx.x;
    __shared__ int cnt[NN];
    int tid = threadIdx.x;
    if (tid < NN) cnt[tid] = 1;          // self loop
    __syncthreads();
    const int* dst = edge_index + BB * EG + g * EG;
    for (int e = tid; e < EG; e += 256)
        atomicAdd(&cnt[dst[e] - g * NN], 1);
    __syncthreads();
    if (tid < NN) g_dis[g * NN + tid] = rsqrtf((float)cnt[tid]);
}

// ============================================================
// Stage 5: GCN aggregate — per-graph block, deterministic CSR
// (rank computed by scan, not by atomic slot grab), then gather
// ============================================================
__global__ __launch_bounds__(256) void aggregate_kernel(
    const int* __restrict__ edge_index,
    const float* __restrict__ gcn_b)
{
    int g = blockIdx.x;
    __shared__ int   s_dst[EG];
    __shared__ int   s_src[EG];
    __shared__ float s_norm[EG];
    __shared__ int   adj_src[EG];
    __shared__ float adj_norm[EG];
    __shared__ int   cnt[NN];
    __shared__ int   start[NN + 1];
    __shared__ float bsm[GH];

    int tid = threadIdx.x;
    const int* srcA = edge_index + g * EG;
    const int* dstA = edge_index + BB * EG + g * EG;

    if (tid < NN) cnt[tid] = 0;
    if (tid < GH) bsm[tid] = gcn_b[tid];
    __syncthreads();

    for (int e = tid; e < EG; e += 256) {
        int s = srcA[e] - g * NN;
        int d = dstA[e] - g * NN;
        s_src[e] = s;
        s_dst[e] = d;
        s_norm[e] = g_dis[g * NN + s] * g_dis[g * NN + d];
        atomicAdd(&cnt[d], 1);
    }
    __syncthreads();

    if (tid == 0) {
        int s = 0;
        for (int i = 0; i < NN; i++) { start[i] = s; s += cnt[i]; }
        start[NN] = s;
    }
    __syncthreads();

    // deterministic placement: edge e goes to slot start[d] + (#earlier edges with same d)
    for (int e = tid; e < EG; e += 256) {
        int d = s_dst[e];
        int r = 0;
        for (int e2 = 0; e2 < e; e2++) r += (s_dst[e2] == d);
        int p = start[d] + r;
        adj_src[p]  = s_src[e];
        adj_norm[p] = s_norm[e];
    }
    __syncthreads();

    // gather: 68 nodes x 128 channels; 2 nodes in flight per iteration
    int ch = tid & 127, half = tid >> 7;
    const float* xwg = g_xw + (size_t)g * NN * GH;
    for (int n0 = half; n0 < NN; n0 += 2) {
        float dis = g_dis[g * NN + n0];
        float acc = dis * dis * xwg[n0 * GH + ch];   // self loop
        int p0 = start[n0], p1 = start[n0 + 1];
        for (int p = p0; p < p1; p++)
            acc = fmaf(adj_norm[p], xwg[adj_src[p] * GH + ch], acc);
        g_h[(size_t)(g * NN + n0) * GH + ch] = fmaxf(acc + bsm[ch], 0.f);
    }
}

// ============================================================
// Stage 6: mean pool + MLP head
// ============================================================
__global__ __launch_bounds__(GH) void head_kernel(
    const float* __restrict__ w1, const float* __restrict__ b1,
    const float* __restrict__ w2, const float* __restrict__ b2,
    float* __restrict__ out)
{
    int b = blockIdx.x;
    int tid = threadIdx.x;
    __shared__ float gsm[GH];
    __shared__ float zsm[GH / 2];

    float s = 0.f;
    for (int i = 0; i < NN; i++)
        s += g_h[(size_t)(b * NN + i) * GH + tid];
    gsm[tid] = s * (1.0f / (float)NN);
    __syncthreads();

    if (tid < GH / 2) {
        float acc = b1[tid];
        #pragma unroll
        for (int c = 0; c < GH; c++)
            acc = fmaf(gsm[c], w1[c * (GH / 2) + tid], acc);
        zsm[tid] = fmaxf(acc, 0.f);
    }
    __syncthreads();

    if (tid < OUTD) {
        float acc = b2[tid];
        for (int j = 0; j < GH / 2; j++)
            acc = fmaf(zsm[j], w2[j * OUTD + tid], acc);
        out[b * OUTD + tid] = acc;
    }
}

extern "C" void kernel_launch(void* const* d_in, const int* in_sizes, int n_in,
                              void* d_out, int out_size)
{
    const float* x        = (const float*)d_in[0];
    const int*   edge_idx = (const int*)  d_in[1];
    const float* conv_w   = (const float*)d_in[3];
    const float* conv_b   = (const float*)d_in[4];
    const float* lin1_w   = (const float*)d_in[5];
    const float* lin1_b   = (const float*)d_in[6];
    const float* gcn_w    = (const float*)d_in[7];
    const float* gcn_b    = (const float*)d_in[8];
    const float* mlp_w1   = (const float*)d_in[9];
    const float* mlp_b1   = (const float*)d_in[10];
    const float* mlp_w2   = (const float*)d_in[11];
    const float* mlp_b2   = (const float*)d_in[12];
    float* out = (float*)d_out;

    conv_pool_kernel<<<TT, 256>>>(x, conv_w, conv_b);
    lin1_kernel<<<dim3(NN, 4), 256>>>(lin1_w, lin1_b);
    gcn_xw_kernel<<<TT / 4, 512>>>(gcn_w);
    deg_kernel<<<BB, 256>>>(edge_idx);
    aggregate_kernel<<<BB, 256>>>(edge_idx, gcn_b);
    head_kernel<<<BB, GH>>>(mlp_w1, mlp_b1, mlp_w2, mlp_b2, out);
}